// round 5
// baseline (speedup 1.0000x reference)
#include <cuda_runtime.h>
#include <math.h>
#include <stdint.h>

#define BB 8
#define DD 256
#define NN 2048
#define NH 4
#define HD 64
#define QTILE 128
#define KTILE 64

typedef unsigned long long u64;
typedef unsigned int u32;

// Scratch. g_q/g_k TRANSPOSED per-head [b][h][tok][dd]; g_v/g_x natural [b][ch][tok].
__device__ float g_q[BB*DD*NN];
__device__ float g_k[BB*DD*NN];
__device__ float g_v[BB*DD*NN];
__device__ float g_x[BB*DD*NN];

// ---------------- packed f32x2 helpers ----------------
__device__ __forceinline__ void ffma2(u64& d, u64 a, u64 b) {
    asm("fma.rn.f32x2 %0, %1, %2, %3;" : "=l"(d) : "l"(a), "l"(b), "l"(d));
}
__device__ __forceinline__ u64 bcast2(float x) {
    u64 r; asm("mov.b64 %0, {%1, %1};" : "=l"(r) : "f"(x)); return r;
}
__device__ __forceinline__ float2 unpk(u64 v) {
    float lo, hi; asm("mov.b64 {%0, %1}, %2;" : "=f"(lo), "=f"(hi) : "l"(v));
    return make_float2(lo, hi);
}
__device__ __forceinline__ u32 f2tf32(float x) {
    u32 r; asm("cvt.rna.tf32.f32 %0, %1;" : "=r"(r) : "f"(x)); return r;
}
__device__ __forceinline__ u32 smem_u32(const void* p) {
    u32 a; asm("{ .reg .u64 t; cvta.to.shared.u64 t, %1; cvt.u32.u64 %0, t; }" : "=r"(a) : "l"(p));
    return a;
}
__device__ __forceinline__ void mma_tf32(float c[4], u32 a0, u32 a1, u32 a2, u32 a3,
                                         u32 b0, u32 b1) {
    asm volatile("mma.sync.aligned.m16n8k8.row.col.f32.tf32.tf32.f32 "
        "{%0,%1,%2,%3}, {%4,%5,%6,%7}, {%8,%9}, {%0,%1,%2,%3};"
        : "+f"(c[0]), "+f"(c[1]), "+f"(c[2]), "+f"(c[3])
        : "r"(a0), "r"(a1), "r"(a2), "r"(a3), "r"(b0), "r"(b1));
}
#define LDSM4(r, a) asm volatile( \
    "ldmatrix.sync.aligned.m8n8.x4.shared.b16 {%0,%1,%2,%3}, [%4];" \
    : "=r"((r)[0]), "=r"((r)[1]), "=r"((r)[2]), "=r"((r)[3]) : "r"(a))
#define LDSM2(r0, r1, a) asm volatile( \
    "ldmatrix.sync.aligned.m8n8.x2.shared.b16 {%0,%1}, [%2];" \
    : "=r"(r0), "=r"(r1) : "r"(a))
#define STS4(a, x, y, z, w_) asm volatile( \
    "st.shared.v4.b32 [%0], {%1,%2,%3,%4};" :: "r"(a), "r"(x), "r"(y), "r"(z), "r"(w_) : "memory")
#define STS2(a, x, y) asm volatile( \
    "st.shared.v2.b32 [%0], {%1,%2};" :: "r"(a), "r"(x), "r"(y) : "memory")

// ---------------------------------------------------------------------------
// Projection GEMM (fp32 exact, f32x2, o-pair packed). 64o x 128n tile, 256 thr.
// TRANS=1 writes per-head transposed [b][h][tok][dd].
// ---------------------------------------------------------------------------
template <int TRANS>
__global__ __launch_bounds__(256) void proj_kernel(
    const float* __restrict__ W, const float* __restrict__ bias,
    const float* __restrict__ X, float* __restrict__ Y)
{
    __shared__ float sW[16*68];    // [kk][oo] 64 + pad
    __shared__ float sX[16*132];   // [kk][nn] 128 + pad

    const int b  = blockIdx.z;
    const int o0 = blockIdx.y * 64;
    const int n0 = blockIdx.x * 128;
    const int t  = threadIdx.x;
    const int tx = t & 31;   // n group (4 n)
    const int ty = t >> 5;   // o group (8 o)

    const float* Xb = X + (size_t)b * DD * NN;
    u64 acc2[4][4];   // [o-pair][n]
#pragma unroll
    for (int i = 0; i < 4; i++)
#pragma unroll
        for (int j = 0; j < 4; j++) acc2[i][j] = 0ull;

    for (int k0 = 0; k0 < DD; k0 += 16) {
#pragma unroll
        for (int i = 0; i < 4; i++) {
            int idx = t + i * 256;
            int oo = idx >> 4, kk = idx & 15;
            sW[kk * 68 + oo] = W[(o0 + oo) * DD + k0 + kk];
        }
#pragma unroll
        for (int i = 0; i < 2; i++) {
            int idx4 = t + i * 256;
            int kk = idx4 >> 5, c4 = idx4 & 31;
            *(float4*)&sX[kk * 132 + c4 * 4] =
                *(const float4*)&Xb[(k0 + kk) * NN + n0 + c4 * 4];
        }
        __syncthreads();
#pragma unroll
        for (int kk = 0; kk < 16; kk++) {
            const ulonglong2 w01 = *(const ulonglong2*)&sW[kk * 68 + ty * 8];
            const ulonglong2 w23 = *(const ulonglong2*)&sW[kk * 68 + ty * 8 + 4];
            const float4 xv = *(const float4*)&sX[kk * 132 + tx * 4];
            u64 x0 = bcast2(xv.x), x1 = bcast2(xv.y), x2 = bcast2(xv.z), x3 = bcast2(xv.w);
            ffma2(acc2[0][0], w01.x, x0); ffma2(acc2[0][1], w01.x, x1);
            ffma2(acc2[0][2], w01.x, x2); ffma2(acc2[0][3], w01.x, x3);
            ffma2(acc2[1][0], w01.y, x0); ffma2(acc2[1][1], w01.y, x1);
            ffma2(acc2[1][2], w01.y, x2); ffma2(acc2[1][3], w01.y, x3);
            ffma2(acc2[2][0], w23.x, x0); ffma2(acc2[2][1], w23.x, x1);
            ffma2(acc2[2][2], w23.x, x2); ffma2(acc2[2][3], w23.x, x3);
            ffma2(acc2[3][0], w23.y, x0); ffma2(acc2[3][1], w23.y, x1);
            ffma2(acc2[3][2], w23.y, x2); ffma2(acc2[3][3], w23.y, x3);
        }
        __syncthreads();
    }

    // unpack: v[oi][n]
    float v[8][4];
#pragma unroll
    for (int op = 0; op < 4; op++)
#pragma unroll
        for (int n = 0; n < 4; n++) {
            float2 p = unpk(acc2[op][n]);
            v[op * 2][n] = p.x;
            v[op * 2 + 1][n] = p.y;
        }
#pragma unroll
    for (int oi = 0; oi < 8; oi++) {
        int o = o0 + ty * 8 + oi;
        float bv = bias[o];
        if (TRANS) {
            int dd = o >> 2, hh = o & 3;
            float* base = Y + (((size_t)b * NH + hh) * NN + n0 + tx * 4) * HD + dd;
#pragma unroll
            for (int n = 0; n < 4; n++) base[n * HD] = v[oi][n] + bv;
        } else {
            float* Yb = Y + (size_t)b * DD * NN;
            *(float4*)&Yb[o * NN + n0 + tx * 4] = make_float4(
                v[oi][0] + bv, v[oi][1] + bv, v[oi][2] + bv, v[oi][3] + bv);
        }
    }
}

// ---------------------------------------------------------------------------
// mma.sync tf32 flash attention, ldmatrix + swizzled natural tiles.
// CTA = (b, h, 128-query tile), 128 threads (4 warps), warp owns 32 q rows.
// Tiles: sQ[128][64], sK[64][64](tok,dd), sV[64][64](dd,tok), sP[128][64].
// Row = 64 u32 = 256 B = 16 chunks of 16 B; chunk' = chunk ^ (row & 7).
// ---------------------------------------------------------------------------
__global__ __launch_bounds__(128) void attn_mma(const int* __restrict__ mask)
{
    extern __shared__ u32 smu[];
    const u32 sbase = smem_u32(smu);
    const u32 Qo = 0;
    const u32 Ko = 8192 * 4;
    const u32 Vo = (8192 + 4096) * 4;
    const u32 Po = (8192 + 8192) * 4;
    int* skm = (int*)(smu + 8192 + 4096 + 4096 + 8192);

    const int t = threadIdx.x;
    const int w = t >> 5, lane = t & 31;
    const int gid = lane >> 2, tig = lane & 3;
    const int b = blockIdx.z, h = blockIdx.y;
    const int q0 = blockIdx.x * QTILE;

    // ---- Q fill (fold 1/8, tf32, swizzled) ----
    const float* qb = g_q + (((size_t)b * NH + h) * NN + q0) * HD;
#pragma unroll
    for (int i = 0; i < 16; i++) {
        int idx = t + i * 128;
        int row = idx >> 4, c = idx & 15;
        float4 v = *(const float4*)(qb + row * HD + c * 4);
        u32 a = sbase + Qo + row * 256 + ((c ^ (row & 7)) << 4);
        STS4(a, f2tf32(v.x * 0.125f), f2tf32(v.y * 0.125f),
                f2tf32(v.z * 0.125f), f2tf32(v.w * 0.125f));
    }
    const int* mb_ = mask + (size_t)b * NN;
    int qm[4];
#pragma unroll
    for (int mi = 0; mi < 2; mi++) {
        qm[2 * mi]     = mb_[q0 + w * 32 + mi * 16 + gid];
        qm[2 * mi + 1] = mb_[q0 + w * 32 + mi * 16 + gid + 8];
    }

    float oc[2][8][4];
#pragma unroll
    for (int mi = 0; mi < 2; mi++)
#pragma unroll
        for (int nb = 0; nb < 8; nb++)
#pragma unroll
            for (int e = 0; e < 4; e++) oc[mi][nb][e] = 0.f;
    float lsum[4] = {0.f, 0.f, 0.f, 0.f};

    const float* kb0 = g_k + (((size_t)b * NH + h) * NN) * HD;
    const float* vb0 = g_v + ((size_t)b * DD + h) * NN;

    // ldmatrix address components
    const int arow0 = w * 32 + (lane & 15);        // A rows (mi adds 16)
    const int ahi = lane >> 4;                     // chunk +1 for col+4 matrices
    const int brow = lane & 7;                     // B rows within nb block
    const int bhi = (lane >> 3) & 1;

    for (int k0 = 0; k0 < NN; k0 += KTILE) {
        __syncthreads();   // prev-iter frag reads of sK/sV done
        // ---- K fill: [tok][dd] ----
#pragma unroll
        for (int i = 0; i < 8; i++) {
            int idx = t + i * 128;
            int row = idx >> 4, c = idx & 15;
            float4 v = *(const float4*)(kb0 + (size_t)(k0 + row) * HD + c * 4);
            u32 a = sbase + Ko + row * 256 + ((c ^ (row & 7)) << 4);
            STS4(a, f2tf32(v.x), f2tf32(v.y), f2tf32(v.z), f2tf32(v.w));
        }
        // ---- V fill: [dd][tok] ----
#pragma unroll
        for (int i = 0; i < 8; i++) {
            int idx = t + i * 128;
            int dd = idx >> 4, c = idx & 15;
            float4 v = *(const float4*)(vb0 + (size_t)dd * (NH * NN) + k0 + c * 4);
            u32 a = sbase + Vo + dd * 256 + ((c ^ (dd & 7)) << 4);
            STS4(a, f2tf32(v.x), f2tf32(v.y), f2tf32(v.z), f2tf32(v.w));
        }
        if (t < KTILE) skm[t] = mb_[k0 + t];
        __syncthreads();

        // ---- S = Q K^T ----
        float sc[2][8][4];
#pragma unroll
        for (int mi = 0; mi < 2; mi++)
#pragma unroll
            for (int nb = 0; nb < 8; nb++)
#pragma unroll
                for (int e = 0; e < 4; e++) sc[mi][nb][e] = 0.f;
#pragma unroll
        for (int ks = 0; ks < 8; ks++) {
            u32 A0[4], A1[4];
            {
                int r = arow0;
                u32 a = sbase + Qo + r * 256 + (((ks * 2 + ahi) ^ (r & 7)) << 4);
                LDSM4(A0, a);
                r = arow0 + 16;
                a = sbase + Qo + r * 256 + (((ks * 2 + ahi) ^ (r & 7)) << 4);
                LDSM4(A1, a);
            }
#pragma unroll
            for (int nb = 0; nb < 8; nb++) {
                int r = nb * 8 + brow;
                u32 a = sbase + Ko + r * 256 + (((ks * 2 + bhi) ^ (r & 7)) << 4);
                u32 B0, B1; LDSM2(B0, B1, a);
                mma_tf32(sc[0][nb], A0[0], A0[1], A0[2], A0[3], B0, B1);
                mma_tf32(sc[1][nb], A1[0], A1[1], A1[2], A1[3], B0, B1);
            }
        }

        // ---- softmax (no-max), P -> sP (warp-private rows) ----
#pragma unroll
        for (int mi = 0; mi < 2; mi++)
#pragma unroll
        for (int nb = 0; nb < 8; nb++) {
            int col0 = nb * 8 + tig * 2;
            int km0 = skm[col0], km1 = skm[col0 + 1];
            float e0 = (qm[2*mi]   && km0) ? __expf(sc[mi][nb][0]) : 0.f;
            float e1 = (qm[2*mi]   && km1) ? __expf(sc[mi][nb][1]) : 0.f;
            float e2 = (qm[2*mi+1] && km0) ? __expf(sc[mi][nb][2]) : 0.f;
            float e3 = (qm[2*mi+1] && km1) ? __expf(sc[mi][nb][3]) : 0.f;
            lsum[2*mi]   += e0 + e1;
            lsum[2*mi+1] += e2 + e3;
            int r = w * 32 + mi * 16 + gid;
            u32 a = sbase + Po + r * 256 + ((((col0 >> 2)) ^ (r & 7)) << 4) + (tig & 1) * 8;
            STS2(a, f2tf32(e0), f2tf32(e1));
            r += 8;
            a = sbase + Po + r * 256 + (((col0 >> 2) ^ (r & 7)) << 4) + (tig & 1) * 8;
            STS2(a, f2tf32(e2), f2tf32(e3));
        }
        __syncwarp();

        // ---- O += P V ----
#pragma unroll
        for (int kt = 0; kt < 8; kt++) {
            u32 A0[4], A1[4];
            {
                int r = arow0;
                u32 a = sbase + Po + r * 256 + (((kt * 2 + ahi) ^ (r & 7)) << 4);
                LDSM4(A0, a);
                r = arow0 + 16;
                a = sbase + Po + r * 256 + (((kt * 2 + ahi) ^ (r & 7)) << 4);
                LDSM4(A1, a);
            }
#pragma unroll
            for (int nb = 0; nb < 8; nb++) {
                int r = nb * 8 + brow;
                u32 a = sbase + Vo + r * 256 + (((kt * 2 + bhi) ^ (r & 7)) << 4);
                u32 B0, B1; LDSM2(B0, B1, a);
                mma_tf32(oc[0][nb], A0[0], A0[1], A0[2], A0[3], B0, B1);
                mma_tf32(oc[1][nb], A1[0], A1[1], A1[2], A1[3], B0, B1);
            }
        }
    }

    // ---- epilogue ----
#pragma unroll
    for (int i = 0; i < 4; i++) {
        lsum[i] += __shfl_xor_sync(~0u, lsum[i], 1);
        lsum[i] += __shfl_xor_sync(~0u, lsum[i], 2);
    }
    float inv[4];
#pragma unroll
    for (int i = 0; i < 4; i++) inv[i] = 1.f / lsum[i];

    float* xb = g_x + ((size_t)b * DD + h) * NN;
#pragma unroll
    for (int mi = 0; mi < 2; mi++) {
        int r0 = q0 + w * 32 + mi * 16 + gid;
        int r1 = r0 + 8;
#pragma unroll
        for (int nb = 0; nb < 8; nb++) {
            int dd0 = nb * 8 + tig * 2;
            xb[(size_t)dd0 * (NH * NN) + r0]       = oc[mi][nb][0] * inv[2*mi];
            xb[(size_t)(dd0 + 1) * (NH * NN) + r0] = oc[mi][nb][1] * inv[2*mi];
            xb[(size_t)dd0 * (NH * NN) + r1]       = oc[mi][nb][2] * inv[2*mi+1];
            xb[(size_t)(dd0 + 1) * (NH * NN) + r1] = oc[mi][nb][3] * inv[2*mi+1];
        }
    }
}

// ---------------------------------------------------------------------------
extern "C" void kernel_launch(void* const* d_in, const int* in_sizes, int n_in,
                              void* d_out, int out_size)
{
    const float* query = (const float*)d_in[0];
    const float* key_  = (const float*)d_in[1];
    const float* value = (const float*)d_in[2];
    const int*   mask  = (const int*)  d_in[3];
    const float* Wq = (const float*)d_in[4];
    const float* bq = (const float*)d_in[5];
    const float* Wk = (const float*)d_in[6];
    const float* bk = (const float*)d_in[7];
    const float* Wv = (const float*)d_in[8];
    const float* bv = (const float*)d_in[9];
    const float* Wm = (const float*)d_in[10];
    const float* bm = (const float*)d_in[11];
    float* out = (float*)d_out;

    float *q, *k, *v, *x;
    cudaGetSymbolAddress((void**)&q, g_q);
    cudaGetSymbolAddress((void**)&k, g_k);
    cudaGetSymbolAddress((void**)&v, g_v);
    cudaGetSymbolAddress((void**)&x, g_x);

    dim3 pgrid(NN / 128, DD / 64, BB);
    proj_kernel<1><<<pgrid, 256>>>(Wq, bq, query, q);
    proj_kernel<1><<<pgrid, 256>>>(Wk, bk, key_,  k);
    proj_kernel<0><<<pgrid, 256>>>(Wv, bv, value, v);

    const int asmem = (8192 + 4096 + 4096 + 8192) * 4 + 64 * 4;  // 98560
    cudaFuncSetAttribute(attn_mma, cudaFuncAttributeMaxDynamicSharedMemorySize, asmem);
    dim3 agrid(NN / QTILE, NH, BB);
    attn_mma<<<agrid, 128, asmem>>>(mask);

    proj_kernel<0><<<pgrid, 256>>>(Wm, bm, x, out);
}